// round 7
// baseline (speedup 1.0000x reference)
#include <cuda_runtime.h>

// EntmaxBisect: alpha=1.5, 50-iter bisection over last dim (4096), rows = 16384.
//
// Math: with p = 1/4095 every positive (Xs_i - t)^p lies in (0.975, 1], so
// sum(Z) >= 1 <=> count(Xs > t) >= 2 <=> second_largest(Xs) > t. Bisection
// depends only on the row top-2; replicated bit-exactly on the reference fp32
// lattice. Early exit when t==tmin is bit-exact: once tmin+diff rounds to tmin,
// all later iterations are no-ops and the reference's final t equals tmin.
//
// Structure: persistent CTAs (608), 1-row register prefetch, and SOFTWARE
// PIPELINING: warp 15 (arbiter-priority) bisects row i while all warps compute
// row i+1's top-2 into a double-buffered smem slot -> only 2 barriers/row.
// Sparsity guard: a thread whose own max is below t skips the pow/normalize
// path entirely (~99.6% of threads).

#define D        4096
#define THREADS  512
#define NWARPS   16
#define N_ITER   50
#define GRID     608
#define BWARP    (NWARPS - 1)

__device__ __forceinline__ void thread_top2(const float4& a, const float4& b,
                                            float& m1, float& m2)
{
    m1 = __int_as_float(0xff800000);   // -inf
    m2 = m1;
    float v, lo;
    v = a.x; lo = fminf(m1, v); m1 = fmaxf(m1, v); m2 = fmaxf(m2, lo);
    v = a.y; lo = fminf(m1, v); m1 = fmaxf(m1, v); m2 = fmaxf(m2, lo);
    v = a.z; lo = fminf(m1, v); m1 = fmaxf(m1, v); m2 = fmaxf(m2, lo);
    v = a.w; lo = fminf(m1, v); m1 = fmaxf(m1, v); m2 = fmaxf(m2, lo);
    v = b.x; lo = fminf(m1, v); m1 = fmaxf(m1, v); m2 = fmaxf(m2, lo);
    v = b.y; lo = fminf(m1, v); m1 = fmaxf(m1, v); m2 = fmaxf(m2, lo);
    v = b.z; lo = fminf(m1, v); m1 = fmaxf(m1, v); m2 = fmaxf(m2, lo);
    v = b.w; lo = fminf(m1, v); m1 = fmaxf(m1, v); m2 = fmaxf(m2, lo);
}

__device__ __forceinline__ void warp_top2(float& m1, float& m2)
{
    #pragma unroll
    for (int off = 16; off > 0; off >>= 1) {
        float b1 = __shfl_down_sync(0xffffffffu, m1, off);
        float b2 = __shfl_down_sync(0xffffffffu, m2, off);
        float lo = fminf(m1, b1);
        m1 = fmaxf(m1, b1);
        m2 = fmaxf(fmaxf(m2, b2), lo);
    }
}

__global__ __launch_bounds__(THREADS, 4)
void entmax_bisect_kernel(const float* __restrict__ X, float* __restrict__ out,
                          int nrows)
{
    const int tid  = threadIdx.x;
    const int lane = tid & 31;
    const int wid  = tid >> 5;

    __shared__ float sm1[2][NWARPS];
    __shared__ float sm2[2][NWARPS];
    __shared__ alignas(16) float ssum[NWARPS];
    __shared__ float sbc;

    const float4* __restrict__ x4 = reinterpret_cast<const float4*>(X);
    float4* __restrict__ o4 = reinterpret_cast<float4*>(out);
    const float NEG_INF = __int_as_float(0xff800000);

    int row = blockIdx.x;
    if (row >= nrows) return;

    // ---- prologue: load row, publish its warp top-2 partials to sm[0] ----
    size_t base = (size_t)row * (D / 4);
    float4 v0 = x4[base + tid];
    float4 v1 = x4[base + tid + THREADS];

    float a1, a2;                              // a1 = this thread's max (sparsity guard)
    thread_top2(v0, v1, a1, a2);
    {
        float w1 = a1, w2 = a2;
        warp_top2(w1, w2);
        if (lane == 0) { sm1[0][wid] = w1; sm2[0][wid] = w2; }
    }

    // prefetch next row (clamped)
    float4 nv0, nv1;
    {
        int pr = row + GRID; if (pr >= nrows) pr = row;
        size_t pb = (size_t)pr * (D / 4);
        nv0 = x4[pb + tid];
        nv1 = x4[pb + tid + THREADS];
    }
    __syncthreads();

    int b = 0;
    while (true) {
        const bool more = (row + GRID) < nrows;

        // ---- stage 1: warp BWARP bisects row i; ALL warps do top-2 of row i+1
        if (wid == BWARP) {
            float M = (lane < NWARPS) ? sm1[b][lane] : NEG_INF;
            float S = (lane < NWARPS) ? sm2[b][lane] : NEG_INF;
            #pragma unroll
            for (int off = 8; off > 0; off >>= 1) {
                float b1 = __shfl_xor_sync(0xffffffffu, M, off);
                float b2 = __shfl_xor_sync(0xffffffffu, S, off);
                float lo = fminf(M, b1);
                M = fmaxf(M, b1);
                S = fmaxf(fmaxf(S, b2), lo);
            }
            M *= 0.5f;                         // exact: top-2 of Xs = 0.5*top-2 of X
            S *= 0.5f;
            // bit-faithful fp32 bisection with bit-exact early exit
            float tmin = M - 1.0f;
            float diff = (M - 0.015625f) - tmin;   // tmax - tmin, 0.015625 = 4096^-0.5
            float t = tmin;
            #pragma unroll 1
            for (int i = 0; i < N_ITER; i++) {
                diff = diff * 0.5f;
                t = tmin + diff;
                if (t == tmin) break;          // converged: all later iters no-ops
                if (S > t) tmin = t;           // == (sum(Z)-1 >= 0)
            }
            if (lane == 0) sbc = t;            // final TESTED t, as in reference
        }
        float n1, n2;                          // next row's per-thread top-2
        thread_top2(nv0, nv1, n1, n2);
        {
            float w1 = n1, w2 = n2;
            warp_top2(w1, w2);
            if (lane == 0) { sm1[b ^ 1][wid] = w1; sm2[b ^ 1][wid] = w2; }
        }
        __syncthreads();                                   // barrier 1

        const float t = sbc;
        const float p = 1.0f / 4095.0f;        // == fp32(1/(d-1))

        // ---- Z phase on row i (sparsity-guarded, in place over v regs) ----
        const bool active = (fmaf(0.5f, a1, -t) > 0.0f);
        float lsum = 0.0f;
        if (active) {                           // ~1-2 threads per row of 512
            float u;
            u = fmaf(0.5f, v0.x, -t); v0.x = (u > 0.0f) ? __powf(u, p) : 0.0f; lsum += v0.x;
            u = fmaf(0.5f, v0.y, -t); v0.y = (u > 0.0f) ? __powf(u, p) : 0.0f; lsum += v0.y;
            u = fmaf(0.5f, v0.z, -t); v0.z = (u > 0.0f) ? __powf(u, p) : 0.0f; lsum += v0.z;
            u = fmaf(0.5f, v0.w, -t); v0.w = (u > 0.0f) ? __powf(u, p) : 0.0f; lsum += v0.w;
            u = fmaf(0.5f, v1.x, -t); v1.x = (u > 0.0f) ? __powf(u, p) : 0.0f; lsum += v1.x;
            u = fmaf(0.5f, v1.y, -t); v1.y = (u > 0.0f) ? __powf(u, p) : 0.0f; lsum += v1.y;
            u = fmaf(0.5f, v1.z, -t); v1.z = (u > 0.0f) ? __powf(u, p) : 0.0f; lsum += v1.z;
            u = fmaf(0.5f, v1.w, -t); v1.w = (u > 0.0f) ? __powf(u, p) : 0.0f; lsum += v1.w;
        }
        #pragma unroll
        for (int off = 16; off > 0; off >>= 1)
            lsum += __shfl_down_sync(0xffffffffu, lsum, off);
        if (lane == 0) ssum[wid] = lsum;
        __syncthreads();                                   // barrier 2

        // ---- normalize + store row i ----
        const size_t ob = (size_t)row * (D / 4);
        if (active) {
            const float4* s4 = reinterpret_cast<const float4*>(ssum);
            float4 A = s4[0], B = s4[1], C = s4[2], E = s4[3];
            float tot = ((A.x + A.y) + (A.z + A.w)) + ((B.x + B.y) + (B.z + B.w))
                      + ((C.x + C.y) + (C.z + C.w)) + ((E.x + E.y) + (E.z + E.w));
            const float inv = 1.0f / tot;
            float4 r0, r1;
            r0.x = v0.x * inv; r0.y = v0.y * inv; r0.z = v0.z * inv; r0.w = v0.w * inv;
            r1.x = v1.x * inv; r1.y = v1.y * inv; r1.z = v1.z * inv; r1.w = v1.w * inv;
            __stcs(&o4[ob + tid], r0);
            __stcs(&o4[ob + tid + THREADS], r1);
        } else {
            const float4 zr = make_float4(0.0f, 0.0f, 0.0f, 0.0f);
            __stcs(&o4[ob + tid], zr);
            __stcs(&o4[ob + tid + THREADS], zr);
        }

        if (!more) break;
        row += GRID;
        b ^= 1;
        v0 = nv0; v1 = nv1; a1 = n1;           // rotate pipeline
        {
            int pr = row + GRID; if (pr >= nrows) pr = row;
            size_t pb = (size_t)pr * (D / 4);
            nv0 = x4[pb + tid];
            nv1 = x4[pb + tid + THREADS];
        }
    }
}

extern "C" void kernel_launch(void* const* d_in, const int* in_sizes, int n_in,
                              void* d_out, int out_size)
{
    const float* X = (const float*)d_in[0];
    float* out = (float*)d_out;
    const int n = in_sizes[0];          // 8*2048*4096
    const int rows = n / D;             // 16384
    entmax_bisect_kernel<<<GRID, THREADS>>>(X, out, rows);
}

// round 9
// speedup vs baseline: 1.0136x; 1.0136x over previous
#include <cuda_runtime.h>

// EntmaxBisect: alpha=1.5, 50-iter bisection over last dim (4096), rows = 16384.
//
// Math: with p = 1/4095 every positive (Xs_i - t)^p lies in (0.975, 1], so
// sum(Z) >= 1 <=> count(Xs > t) >= 2 <=> second_largest(Xs) > t. Bisection
// depends only on the row top-2, replicated bit-exactly on the reference fp32
// lattice. Early exit when tmin+diff rounds to tmin is bit-exact (RN is
// monotone in diff; all later reference iterations are no-ops).
//
// Structure: persistent CTAs (608 = 4/SM), prefetch for row i+1 issued at the
// TOP of iteration i, consumed at rotation (full-iteration distance — R7
// lesson). Combine+bisect run REDUNDANTLY by every warp; ALL 32 lanes load
// sm[lane & 15] so the 16-wide butterfly reduces correctly in BOTH half-warps
// (R8 bug: upper lanes seeded with -inf got t=NaN). 2 barriers/row. Sparsity
// guard: thread whose own max is below t skips pow/normalize (~99.6%).

#define D        4096
#define THREADS  512
#define NWARPS   16
#define N_ITER   50
#define GRID     608

__device__ __forceinline__ void thread_top2(const float4& a, const float4& b,
                                            float& m1, float& m2)
{
    m1 = __int_as_float(0xff800000);   // -inf
    m2 = m1;
    float v, lo;
    v = a.x; lo = fminf(m1, v); m1 = fmaxf(m1, v); m2 = fmaxf(m2, lo);
    v = a.y; lo = fminf(m1, v); m1 = fmaxf(m1, v); m2 = fmaxf(m2, lo);
    v = a.z; lo = fminf(m1, v); m1 = fmaxf(m1, v); m2 = fmaxf(m2, lo);
    v = a.w; lo = fminf(m1, v); m1 = fmaxf(m1, v); m2 = fmaxf(m2, lo);
    v = b.x; lo = fminf(m1, v); m1 = fmaxf(m1, v); m2 = fmaxf(m2, lo);
    v = b.y; lo = fminf(m1, v); m1 = fmaxf(m1, v); m2 = fmaxf(m2, lo);
    v = b.z; lo = fminf(m1, v); m1 = fmaxf(m1, v); m2 = fmaxf(m2, lo);
    v = b.w; lo = fminf(m1, v); m1 = fmaxf(m1, v); m2 = fmaxf(m2, lo);
}

__global__ __launch_bounds__(THREADS, 4)
void entmax_bisect_kernel(const float* __restrict__ X, float* __restrict__ out,
                          int nrows)
{
    const int tid  = threadIdx.x;
    const int lane = tid & 31;
    const int wid  = tid >> 5;

    __shared__ float sm1[NWARPS];
    __shared__ float sm2[NWARPS];
    __shared__ alignas(16) float ssum[NWARPS];

    const float4* __restrict__ x4 = reinterpret_cast<const float4*>(X);
    float4* __restrict__ o4 = reinterpret_cast<float4*>(out);

    int row = blockIdx.x;
    if (row >= nrows) return;

    size_t base = (size_t)row * (D / 4);
    float4 v0 = x4[base + tid];
    float4 v1 = x4[base + tid + THREADS];

    while (true) {
        const int  nrow = row + GRID;
        const bool more = (nrow < nrows);
        // ---- prefetch next row NOW; consumed only at the end-of-iter rotate
        const size_t pb = (size_t)(more ? nrow : row) * (D / 4);
        float4 nv0 = x4[pb + tid];
        float4 nv1 = x4[pb + tid + THREADS];

        // ---- per-thread top-2 of raw X (a1 kept as sparsity guard) ----
        float a1, a2;
        thread_top2(v0, v1, a1, a2);

        // ---- warp top-2 reduce ----
        float w1 = a1, w2 = a2;
        #pragma unroll
        for (int off = 16; off > 0; off >>= 1) {
            float b1 = __shfl_down_sync(0xffffffffu, w1, off);
            float b2 = __shfl_down_sync(0xffffffffu, w2, off);
            float lo = fminf(w1, b1);
            w1 = fmaxf(w1, b1);
            w2 = fmaxf(fmaxf(w2, b2), lo);
        }
        if (lane == 0) { sm1[wid] = w1; sm2[wid] = w2; }
        __syncthreads();                                    // barrier 1

        // ---- EVERY warp: combine 16 partials + bisect (redundant, parallel)
        // All 32 lanes read sm[lane & 15]: both half-warps hold the full set,
        // so the 16-wide xor butterfly reduces correctly in each half.
        float t;
        {
            float M = sm1[lane & (NWARPS - 1)];
            float S = sm2[lane & (NWARPS - 1)];
            #pragma unroll
            for (int off = 8; off > 0; off >>= 1) {
                float b1 = __shfl_xor_sync(0xffffffffu, M, off);
                float b2 = __shfl_xor_sync(0xffffffffu, S, off);
                float lo = fminf(M, b1);
                M = fmaxf(M, b1);
                S = fmaxf(fmaxf(S, b2), lo);
            }
            M *= 0.5f;                       // exact: top-2 of Xs = 0.5*top-2 of X
            S *= 0.5f;
            // bit-faithful fp32 bisection with bit-exact early exit
            float tmin = M - 1.0f;
            float diff = (M - 0.015625f) - tmin;   // tmax - tmin
            t = tmin;
            #pragma unroll 1
            for (int i = 0; i < N_ITER; i++) {
                diff = diff * 0.5f;
                t = tmin + diff;
                if (t == tmin) break;        // converged: all later iters no-op
                if (S > t) tmin = t;         // == (sum(Z)-1 >= 0)
            }
        }

        const float p = 1.0f / 4095.0f;      // == fp32(1/(d-1))

        // ---- Z phase (sparsity-guarded, in place over v regs) ----
        const bool active = (fmaf(0.5f, a1, -t) > 0.0f);
        float lsum = 0.0f;
        if (active) {                         // ~1-2 threads per row of 512
            float u;
            u = fmaf(0.5f, v0.x, -t); v0.x = (u > 0.0f) ? __powf(u, p) : 0.0f; lsum += v0.x;
            u = fmaf(0.5f, v0.y, -t); v0.y = (u > 0.0f) ? __powf(u, p) : 0.0f; lsum += v0.y;
            u = fmaf(0.5f, v0.z, -t); v0.z = (u > 0.0f) ? __powf(u, p) : 0.0f; lsum += v0.z;
            u = fmaf(0.5f, v0.w, -t); v0.w = (u > 0.0f) ? __powf(u, p) : 0.0f; lsum += v0.w;
            u = fmaf(0.5f, v1.x, -t); v1.x = (u > 0.0f) ? __powf(u, p) : 0.0f; lsum += v1.x;
            u = fmaf(0.5f, v1.y, -t); v1.y = (u > 0.0f) ? __powf(u, p) : 0.0f; lsum += v1.y;
            u = fmaf(0.5f, v1.z, -t); v1.z = (u > 0.0f) ? __powf(u, p) : 0.0f; lsum += v1.z;
            u = fmaf(0.5f, v1.w, -t); v1.w = (u > 0.0f) ? __powf(u, p) : 0.0f; lsum += v1.w;
        }
        #pragma unroll
        for (int off = 16; off > 0; off >>= 1)
            lsum += __shfl_down_sync(0xffffffffu, lsum, off);
        if (lane == 0) ssum[wid] = lsum;
        __syncthreads();                                    // barrier 2

        // ---- normalize + store ----
        const size_t ob = (size_t)row * (D / 4);
        if (active) {
            const float4* s4 = reinterpret_cast<const float4*>(ssum);
            float4 A = s4[0], B = s4[1], C = s4[2], E = s4[3];
            float tot = ((A.x + A.y) + (A.z + A.w)) + ((B.x + B.y) + (B.z + B.w))
                      + ((C.x + C.y) + (C.z + C.w)) + ((E.x + E.y) + (E.z + E.w));
            const float inv = 1.0f / tot;
            float4 r0, r1;
            r0.x = v0.x * inv; r0.y = v0.y * inv; r0.z = v0.z * inv; r0.w = v0.w * inv;
            r1.x = v1.x * inv; r1.y = v1.y * inv; r1.z = v1.z * inv; r1.w = v1.w * inv;
            __stcs(&o4[ob + tid], r0);
            __stcs(&o4[ob + tid + THREADS], r1);
        } else {
            const float4 zr = make_float4(0.0f, 0.0f, 0.0f, 0.0f);
            __stcs(&o4[ob + tid], zr);
            __stcs(&o4[ob + tid + THREADS], zr);
        }

        if (!more) break;
        v0 = nv0; v1 = nv1;                   // consume prefetch (full-iter distance)
        row = nrow;
    }
}

extern "C" void kernel_launch(void* const* d_in, const int* in_sizes, int n_in,
                              void* d_out, int out_size)
{
    const float* X = (const float*)d_in[0];
    float* out = (float*)d_out;
    const int n = in_sizes[0];          // 8*2048*4096
    const int rows = n / D;             // 16384
    entmax_bisect_kernel<<<GRID, THREADS>>>(X, out, rows);
}

// round 10
// speedup vs baseline: 1.1840x; 1.1681x over previous
#include <cuda_runtime.h>

// EntmaxBisect: alpha=1.5, 50-iter bisection over last dim (4096), rows = 16384.
//
// Math: with p = 1/4095 every positive (Xs_i - t)^p lies in (0.975, 1], so
// sum(Z) >= 1 <=> count(Xs > t) >= 2 <=> second_largest(Xs) > t. Bisection
// depends only on the row top-2, replicated bit-exactly on the reference fp32
// lattice. Early exit when tmin+diff rounds to tmin is bit-exact (RN monotone
// in diff; all later reference iterations are no-ops, final tested t == tmin).
//
// Structure (R6-proven skeleton): persistent CTAs (608 = 4/SM x 152 SM),
// prefetch for row i+1 issued at the TOP of iteration i, consumed at rotation
// (full-iteration distance). Bisect runs in warp 0 ONLY (R9 lesson: redundant
// per-warp bisect explodes issue). NEW: one-time startup stagger de-phases the
// 4 co-resident CTAs per SM (bid/152 quarter-period offsets) so their memory
// bursts fill each other's barrier/bisect gaps. Sparsity guard: thread whose
// own max is below t skips pow/normalize (~99.6% of threads).

#define D        4096
#define THREADS  512
#define NWARPS   16
#define N_ITER   50
#define GRID     608
#define NSM      152
#define STAGGER  1550u   // ~quarter of the measured per-row period (cycles)

__device__ __forceinline__ void thread_top2(const float4& a, const float4& b,
                                            float& m1, float& m2)
{
    m1 = __int_as_float(0xff800000);   // -inf
    m2 = m1;
    float v, lo;
    v = a.x; lo = fminf(m1, v); m1 = fmaxf(m1, v); m2 = fmaxf(m2, lo);
    v = a.y; lo = fminf(m1, v); m1 = fmaxf(m1, v); m2 = fmaxf(m2, lo);
    v = a.z; lo = fminf(m1, v); m1 = fmaxf(m1, v); m2 = fmaxf(m2, lo);
    v = a.w; lo = fminf(m1, v); m1 = fmaxf(m1, v); m2 = fmaxf(m2, lo);
    v = b.x; lo = fminf(m1, v); m1 = fmaxf(m1, v); m2 = fmaxf(m2, lo);
    v = b.y; lo = fminf(m1, v); m1 = fmaxf(m1, v); m2 = fmaxf(m2, lo);
    v = b.z; lo = fminf(m1, v); m1 = fmaxf(m1, v); m2 = fmaxf(m2, lo);
    v = b.w; lo = fminf(m1, v); m1 = fmaxf(m1, v); m2 = fmaxf(m2, lo);
}

__global__ __launch_bounds__(THREADS, 4)
void entmax_bisect_kernel(const float* __restrict__ X, float* __restrict__ out,
                          int nrows)
{
    const int tid  = threadIdx.x;
    const int lane = tid & 31;
    const int wid  = tid >> 5;

    __shared__ float sm1[NWARPS];
    __shared__ float sm2[NWARPS];
    __shared__ alignas(16) float ssum[NWARPS];
    __shared__ float sbc;

    const float4* __restrict__ x4 = reinterpret_cast<const float4*>(X);
    float4* __restrict__ o4 = reinterpret_cast<float4*>(out);

    int row = blockIdx.x;
    if (row >= nrows) return;

    // ---- one-time de-phasing of the 4 co-resident CTAs on each SM ----
    {
        unsigned q = (unsigned)(blockIdx.x / NSM) & 3u;
        if (q) {
            unsigned long long tgt = clock64() + (unsigned long long)q * STAGGER;
            while (clock64() < tgt) { }
        }
    }

    size_t base = (size_t)row * (D / 4);
    float4 v0 = x4[base + tid];
    float4 v1 = x4[base + tid + THREADS];

    while (true) {
        const int  nrow = row + GRID;
        const bool more = (nrow < nrows);
        // ---- prefetch next row NOW; consumed only at the end-of-iter rotate
        const size_t pb = (size_t)(more ? nrow : row) * (D / 4);
        float4 nv0 = x4[pb + tid];
        float4 nv1 = x4[pb + tid + THREADS];

        // ---- per-thread top-2 of raw X (a1 kept as sparsity guard) ----
        float a1, a2;
        thread_top2(v0, v1, a1, a2);

        // ---- warp top-2 reduce ----
        float w1 = a1, w2 = a2;
        #pragma unroll
        for (int off = 16; off > 0; off >>= 1) {
            float b1 = __shfl_down_sync(0xffffffffu, w1, off);
            float b2 = __shfl_down_sync(0xffffffffu, w2, off);
            float lo = fminf(w1, b1);
            w1 = fmaxf(w1, b1);
            w2 = fmaxf(fmaxf(w2, b2), lo);
        }
        if (lane == 0) { sm1[wid] = w1; sm2[wid] = w2; }
        __syncthreads();                                    // sync1

        // ---- warp 0 ONLY: combine 16 partials + early-exit bisect ----
        if (wid == 0) {
            float M = sm1[lane & (NWARPS - 1)];
            float S = sm2[lane & (NWARPS - 1)];
            #pragma unroll
            for (int off = 8; off > 0; off >>= 1) {
                float b1 = __shfl_xor_sync(0xffffffffu, M, off);
                float b2 = __shfl_xor_sync(0xffffffffu, S, off);
                float lo = fminf(M, b1);
                M = fmaxf(M, b1);
                S = fmaxf(fmaxf(S, b2), lo);
            }
            M *= 0.5f;                       // exact: top-2 of Xs = 0.5*top-2 of X
            S *= 0.5f;
            // bit-faithful fp32 bisection with bit-exact early exit
            float tmin = M - 1.0f;
            float diff = (M - 0.015625f) - tmin;   // tmax - tmin; 1/64 = 4096^-0.5
            float t = tmin;
            #pragma unroll 1
            for (int i = 0; i < N_ITER; i++) {
                diff = diff * 0.5f;
                t = tmin + diff;
                if (t == tmin) break;        // converged: all later iters no-op
                if (S > t) tmin = t;         // == (sum(Z)-1 >= 0)
            }
            if (lane == 0) sbc = t;          // final TESTED t, as in reference
        }
        __syncthreads();                                    // sync2

        const float t = sbc;
        const float p = 1.0f / 4095.0f;      // == fp32(1/(d-1))

        // ---- Z phase (sparsity-guarded, in place over v regs) ----
        const bool active = (fmaf(0.5f, a1, -t) > 0.0f);
        float lsum = 0.0f;
        if (active) {                         // ~1-2 threads per row of 512
            float u;
            u = fmaf(0.5f, v0.x, -t); v0.x = (u > 0.0f) ? __powf(u, p) : 0.0f; lsum += v0.x;
            u = fmaf(0.5f, v0.y, -t); v0.y = (u > 0.0f) ? __powf(u, p) : 0.0f; lsum += v0.y;
            u = fmaf(0.5f, v0.z, -t); v0.z = (u > 0.0f) ? __powf(u, p) : 0.0f; lsum += v0.z;
            u = fmaf(0.5f, v0.w, -t); v0.w = (u > 0.0f) ? __powf(u, p) : 0.0f; lsum += v0.w;
            u = fmaf(0.5f, v1.x, -t); v1.x = (u > 0.0f) ? __powf(u, p) : 0.0f; lsum += v1.x;
            u = fmaf(0.5f, v1.y, -t); v1.y = (u > 0.0f) ? __powf(u, p) : 0.0f; lsum += v1.y;
            u = fmaf(0.5f, v1.z, -t); v1.z = (u > 0.0f) ? __powf(u, p) : 0.0f; lsum += v1.z;
            u = fmaf(0.5f, v1.w, -t); v1.w = (u > 0.0f) ? __powf(u, p) : 0.0f; lsum += v1.w;
        }
        #pragma unroll
        for (int off = 16; off > 0; off >>= 1)
            lsum += __shfl_down_sync(0xffffffffu, lsum, off);
        if (lane == 0) ssum[wid] = lsum;
        __syncthreads();                                    // sync3

        // ---- normalize + store ----
        const size_t ob = (size_t)row * (D / 4);
        if (active) {
            const float4* s4 = reinterpret_cast<const float4*>(ssum);
            float4 A = s4[0], B = s4[1], C = s4[2], E = s4[3];
            float tot = ((A.x + A.y) + (A.z + A.w)) + ((B.x + B.y) + (B.z + B.w))
                      + ((C.x + C.y) + (C.z + C.w)) + ((E.x + E.y) + (E.z + E.w));
            const float inv = 1.0f / tot;
            float4 r0, r1;
            r0.x = v0.x * inv; r0.y = v0.y * inv; r0.z = v0.z * inv; r0.w = v0.w * inv;
            r1.x = v1.x * inv; r1.y = v1.y * inv; r1.z = v1.z * inv; r1.w = v1.w * inv;
            __stcs(&o4[ob + tid], r0);
            __stcs(&o4[ob + tid + THREADS], r1);
        } else {
            const float4 zr = make_float4(0.0f, 0.0f, 0.0f, 0.0f);
            __stcs(&o4[ob + tid], zr);
            __stcs(&o4[ob + tid + THREADS], zr);
        }

        if (!more) break;
        v0 = nv0; v1 = nv1;                   // consume prefetch (full-iter distance)
        row = nrow;
    }
}

extern "C" void kernel_launch(void* const* d_in, const int* in_sizes, int n_in,
                              void* d_out, int out_size)
{
    const float* X = (const float*)d_in[0];
    float* out = (float*)d_out;
    const int n = in_sizes[0];          // 8*2048*4096
    const int rows = n / D;             // 16384
    entmax_bisect_kernel<<<GRID, THREADS>>>(X, out, rows);
}

// round 11
// speedup vs baseline: 1.1874x; 1.0029x over previous
#include <cuda_runtime.h>

// EntmaxBisect: alpha=1.5, 50-iter bisection over last dim (4096), rows = 16384.
//
// Math: with p = 1/4095 every positive (Xs_i - t)^p lies in (0.975, 1], so
// sum(Z) >= 1 <=> count(Xs > t) >= 2 <=> second_largest(Xs) > t. Bisection
// depends only on the row top-2, replicated bit-exactly on the reference fp32
// lattice. The 50-iter loop is FULLY UNROLLED AND BRANCHLESS: the diff-halving
// ladder is exact fp32 (0.98*2^-i, never subnormal) and forms an independent
// chain; per-iter critical path is FADD -> FSETP/FSEL (pred-as-data). Once
// tmin+diff rounds to tmin, remaining iterations are arithmetic no-ops, so
// running all 50 is bit-identical to the reference.
//
// Structure (R10-proven): persistent CTAs (608 = 4/SM x 152 SM), prefetch for
// row i+1 issued at the TOP of iteration i, consumed at rotation. Bisect in
// warp 0 only (R9 lesson). One-time startup stagger de-phases the 4 co-resident
// CTAs per SM. Sparsity guard: thread whose own max is below t skips
// pow/normalize entirely (~99.6% of threads).

#define D        4096
#define THREADS  512
#define NWARPS   16
#define N_ITER   50
#define GRID     608
#define NSM      152
#define STAGGER  1550u

__device__ __forceinline__ void thread_top2(const float4& a, const float4& b,
                                            float& m1, float& m2)
{
    m1 = __int_as_float(0xff800000);   // -inf
    m2 = m1;
    float v, lo;
    v = a.x; lo = fminf(m1, v); m1 = fmaxf(m1, v); m2 = fmaxf(m2, lo);
    v = a.y; lo = fminf(m1, v); m1 = fmaxf(m1, v); m2 = fmaxf(m2, lo);
    v = a.z; lo = fminf(m1, v); m1 = fmaxf(m1, v); m2 = fmaxf(m2, lo);
    v = a.w; lo = fminf(m1, v); m1 = fmaxf(m1, v); m2 = fmaxf(m2, lo);
    v = b.x; lo = fminf(m1, v); m1 = fmaxf(m1, v); m2 = fmaxf(m2, lo);
    v = b.y; lo = fminf(m1, v); m1 = fmaxf(m1, v); m2 = fmaxf(m2, lo);
    v = b.z; lo = fminf(m1, v); m1 = fmaxf(m1, v); m2 = fmaxf(m2, lo);
    v = b.w; lo = fminf(m1, v); m1 = fmaxf(m1, v); m2 = fmaxf(m2, lo);
}

__global__ __launch_bounds__(THREADS, 4)
void entmax_bisect_kernel(const float* __restrict__ X, float* __restrict__ out,
                          int nrows)
{
    const int tid  = threadIdx.x;
    const int lane = tid & 31;
    const int wid  = tid >> 5;

    __shared__ float sm1[NWARPS];
    __shared__ float sm2[NWARPS];
    __shared__ alignas(16) float ssum[NWARPS];
    __shared__ float sbc;

    const float4* __restrict__ x4 = reinterpret_cast<const float4*>(X);
    float4* __restrict__ o4 = reinterpret_cast<float4*>(out);

    int row = blockIdx.x;
    if (row >= nrows) return;

    // ---- one-time de-phasing of the 4 co-resident CTAs on each SM ----
    {
        unsigned q = (unsigned)(blockIdx.x / NSM) & 3u;
        if (q) {
            unsigned long long tgt = clock64() + (unsigned long long)q * STAGGER;
            while (clock64() < tgt) { }
        }
    }

    size_t base = (size_t)row * (D / 4);
    float4 v0 = x4[base + tid];
    float4 v1 = x4[base + tid + THREADS];

    while (true) {
        const int  nrow = row + GRID;
        const bool more = (nrow < nrows);
        // ---- prefetch next row NOW; consumed only at the end-of-iter rotate
        const size_t pb = (size_t)(more ? nrow : row) * (D / 4);
        float4 nv0 = x4[pb + tid];
        float4 nv1 = x4[pb + tid + THREADS];

        // ---- per-thread top-2 of raw X (a1 kept as sparsity guard) ----
        float a1, a2;
        thread_top2(v0, v1, a1, a2);

        // ---- warp top-2 reduce ----
        float w1 = a1, w2 = a2;
        #pragma unroll
        for (int off = 16; off > 0; off >>= 1) {
            float b1 = __shfl_down_sync(0xffffffffu, w1, off);
            float b2 = __shfl_down_sync(0xffffffffu, w2, off);
            float lo = fminf(w1, b1);
            w1 = fmaxf(w1, b1);
            w2 = fmaxf(fmaxf(w2, b2), lo);
        }
        if (lane == 0) { sm1[wid] = w1; sm2[wid] = w2; }
        __syncthreads();                                    // sync1

        // ---- warp 0 ONLY: combine 16 partials + branchless unrolled bisect
        if (wid == 0) {
            float M = sm1[lane & (NWARPS - 1)];
            float S = sm2[lane & (NWARPS - 1)];
            #pragma unroll
            for (int off = 8; off > 0; off >>= 1) {
                float b1 = __shfl_xor_sync(0xffffffffu, M, off);
                float b2 = __shfl_xor_sync(0xffffffffu, S, off);
                float lo = fminf(M, b1);
                M = fmaxf(M, b1);
                S = fmaxf(fmaxf(S, b2), lo);
            }
            M *= 0.5f;                       // exact: top-2 of Xs = 0.5*top-2 of X
            S *= 0.5f;
            // bit-faithful fp32 bisection, fully unrolled, branch-free.
            float tmin = M - 1.0f;
            float diff = (M - 0.015625f) - tmin;   // tmax - tmin
            float t = tmin;
            #pragma unroll
            for (int i = 0; i < N_ITER; i++) {
                diff = diff * 0.5f;          // exact, independent chain
                t = tmin + diff;
                tmin = (S > t) ? t : tmin;   // FSETP/FSEL, no branch
            }
            if (lane == 0) sbc = t;          // final tested t == reference's
        }
        __syncthreads();                                    // sync2

        const float t = sbc;
        const float p = 1.0f / 4095.0f;      // == fp32(1/(d-1))

        // ---- Z phase (sparsity-guarded, in place over v regs) ----
        const bool active = (fmaf(0.5f, a1, -t) > 0.0f);
        float lsum = 0.0f;
        if (active) {                         // ~1-2 threads per row of 512
            float u;
            u = fmaf(0.5f, v0.x, -t); v0.x = (u > 0.0f) ? __powf(u, p) : 0.0f; lsum += v0.x;
            u = fmaf(0.5f, v0.y, -t); v0.y = (u > 0.0f) ? __powf(u, p) : 0.0f; lsum += v0.y;
            u = fmaf(0.5f, v0.z, -t); v0.z = (u > 0.0f) ? __powf(u, p) : 0.0f; lsum += v0.z;
            u = fmaf(0.5f, v0.w, -t); v0.w = (u > 0.0f) ? __powf(u, p) : 0.0f; lsum += v0.w;
            u = fmaf(0.5f, v1.x, -t); v1.x = (u > 0.0f) ? __powf(u, p) : 0.0f; lsum += v1.x;
            u = fmaf(0.5f, v1.y, -t); v1.y = (u > 0.0f) ? __powf(u, p) : 0.0f; lsum += v1.y;
            u = fmaf(0.5f, v1.z, -t); v1.z = (u > 0.0f) ? __powf(u, p) : 0.0f; lsum += v1.z;
            u = fmaf(0.5f, v1.w, -t); v1.w = (u > 0.0f) ? __powf(u, p) : 0.0f; lsum += v1.w;
        }
        #pragma unroll
        for (int off = 16; off > 0; off >>= 1)
            lsum += __shfl_down_sync(0xffffffffu, lsum, off);
        if (lane == 0) ssum[wid] = lsum;
        __syncthreads();                                    // sync3

        // ---- normalize + store ----
        const size_t ob = (size_t)row * (D / 4);
        if (active) {
            const float4* s4 = reinterpret_cast<const float4*>(ssum);
            float4 A = s4[0], B = s4[1], C = s4[2], E = s4[3];
            float tot = ((A.x + A.y) + (A.z + A.w)) + ((B.x + B.y) + (B.z + B.w))
                      + ((C.x + C.y) + (C.z + C.w)) + ((E.x + E.y) + (E.z + E.w));
            const float inv = 1.0f / tot;
            float4 r0, r1;
            r0.x = v0.x * inv; r0.y = v0.y * inv; r0.z = v0.z * inv; r0.w = v0.w * inv;
            r1.x = v1.x * inv; r1.y = v1.y * inv; r1.z = v1.z * inv; r1.w = v1.w * inv;
            __stcs(&o4[ob + tid], r0);
            __stcs(&o4[ob + tid + THREADS], r1);
        } else {
            const float4 zr = make_float4(0.0f, 0.0f, 0.0f, 0.0f);
            __stcs(&o4[ob + tid], zr);
            __stcs(&o4[ob + tid + THREADS], zr);
        }

        if (!more) break;
        v0 = nv0; v1 = nv1;                   // consume prefetch (full-iter distance)
        row = nrow;
    }
}

extern "C" void kernel_launch(void* const* d_in, const int* in_sizes, int n_in,
                              void* d_out, int out_size)
{
    const float* X = (const float*)d_in[0];
    float* out = (float*)d_out;
    const int n = in_sizes[0];          // 8*2048*4096
    const int rows = n / D;             // 16384
    entmax_bisect_kernel<<<GRID, THREADS>>>(X, out, rows);
}

// round 12
// speedup vs baseline: 1.2666x; 1.0666x over previous
#include <cuda_runtime.h>
#include <cstdint>

// EntmaxBisect: alpha=1.5, 50-iter bisection over last dim (4096), rows = 16384.
//
// Math: with p = 1/4095 every positive (Xs_i - t)^p lies in (0.975, 1], so
// sum(Z) >= 1 <=> count(Xs > t) >= 2 <=> second_largest(Xs) > t. Bisection
// depends only on the row top-2, replicated bit-exactly on the reference fp32
// lattice; fully unrolled branch-free (iterations past convergence are exact
// no-ops, so 50 iters == reference bit-for-bit).
//
// Structure: persistent CTAs (608 = 4/SM x 152 SM). Loads via cp.async.bulk
// (UBLKCP) into a 2-slot smem ring with mbarrier complete_tx — 32KB/CTA of
// DMA depth, no register cost, no per-warp LDG bursts. Slot s is re-issued at
// sync1, after all threads finished reading it. Bisect in warp 0 only.
// One-time startup stagger de-phases the 4 co-resident CTAs per SM. Sparsity
// guard: thread whose own max is below t skips pow/normalize (~99.6%).

#define D         4096
#define ROW_BYTES 16384
#define THREADS   512
#define NWARPS    16
#define N_ITER    50
#define GRID      608
#define NSM       152
#define STAGGER   1550u

__device__ __forceinline__ unsigned smem_u32(const void* p) {
    unsigned a;
    asm("{ .reg .u64 t; cvta.to.shared.u64 t, %1; cvt.u32.u64 %0, t; }"
        : "=r"(a) : "l"(p));
    return a;
}

__device__ __forceinline__ void mbar_init(unsigned mb, unsigned cnt) {
    asm volatile("mbarrier.init.shared.b64 [%0], %1;" :: "r"(mb), "r"(cnt) : "memory");
}
__device__ __forceinline__ void mbar_expect_tx(unsigned mb, unsigned bytes) {
    asm volatile("mbarrier.arrive.expect_tx.shared.b64 _, [%0], %1;"
                 :: "r"(mb), "r"(bytes) : "memory");
}
__device__ __forceinline__ void bulk_g2s(unsigned dst, const void* src, unsigned mb) {
    asm volatile(
        "cp.async.bulk.shared::cluster.global.mbarrier::complete_tx::bytes "
        "[%0], [%1], %2, [%3];"
        :: "r"(dst), "l"(src), "r"((unsigned)ROW_BYTES), "r"(mb) : "memory");
}
__device__ __forceinline__ void mbar_wait(unsigned mb, unsigned parity) {
    unsigned done;
    asm volatile(
        "{\n\t.reg .pred p;\n\t"
        "mbarrier.try_wait.parity.acquire.cta.shared::cta.b64 p, [%1], %2;\n\t"
        "selp.b32 %0, 1, 0, p;\n\t}"
        : "=r"(done) : "r"(mb), "r"(parity) : "memory");
    if (!done) {
        asm volatile(
            "{\n\t.reg .pred P1;\n\t"
            "WL_%=:\n\t"
            "mbarrier.try_wait.parity.acquire.cta.shared::cta.b64 P1, [%0], %1, 0x989680;\n\t"
            "@P1 bra.uni WD_%=;\n\t"
            "bra.uni WL_%=;\n\t"
            "WD_%=:\n\t}"
            :: "r"(mb), "r"(parity) : "memory");
    }
}

__global__ __launch_bounds__(THREADS, 4)
void entmax_bisect_kernel(const float* __restrict__ X, float* __restrict__ out,
                          int nrows)
{
    const int tid  = threadIdx.x;
    const int lane = tid & 31;
    const int wid  = tid >> 5;

    __shared__ alignas(16) float4 ring[2][D / 4];       // 2 x 16 KB
    __shared__ float sm1[NWARPS];
    __shared__ float sm2[NWARPS];
    __shared__ alignas(16) float ssum[NWARPS];
    __shared__ float sbc;
    __shared__ alignas(8) unsigned long long mbar_store[2];

    const unsigned mb0 = smem_u32(&mbar_store[0]);
    const unsigned mb1 = smem_u32(&mbar_store[1]);
    const unsigned rg0 = smem_u32(&ring[0][0]);
    const unsigned rg1 = smem_u32(&ring[1][0]);

    float4* __restrict__ o4 = reinterpret_cast<float4*>(out);

    int row = blockIdx.x;
    if (row >= nrows) return;

    // ---- one-time de-phasing of the 4 co-resident CTAs on each SM ----
    {
        unsigned q = (unsigned)(blockIdx.x / NSM) & 3u;
        if (q) {
            unsigned long long tgt = clock64() + (unsigned long long)q * STAGGER;
            while (clock64() < tgt) { }
        }
    }

    // ---- prologue: init mbarriers, kick off DMA for rows row, row+GRID ----
    if (tid == 0) { mbar_init(mb0, 1); mbar_init(mb1, 1); }
    __syncthreads();
    if (tid == 0) {
        mbar_expect_tx(mb0, ROW_BYTES);
        bulk_g2s(rg0, X + (size_t)row * D, mb0);
        int r1 = (row + GRID < nrows) ? row + GRID : row;
        mbar_expect_tx(mb1, ROW_BYTES);
        bulk_g2s(rg1, X + (size_t)r1 * D, mb1);
    }

    int j = 0;                                  // iteration index
    while (true) {
        const int  s  = j & 1;
        const unsigned mb = s ? mb1 : mb0;
        const unsigned rg = s ? rg1 : rg0;
        const bool more = (row + GRID) < nrows;

        // ---- wait DMA for this row, read 8 floats from smem ----
        mbar_wait(mb, (unsigned)((j >> 1) & 1));
        const float4* rbuf = s ? ring[1] : ring[0];
        float4 v0 = rbuf[tid];
        float4 v1 = rbuf[tid + THREADS];

        // ---- per-thread top-2 of raw X (a1 kept as sparsity guard) ----
        float a1 = __int_as_float(0xff800000), a2 = a1;
        {
            float v, lo;
            v = v0.x; lo = fminf(a1, v); a1 = fmaxf(a1, v); a2 = fmaxf(a2, lo);
            v = v0.y; lo = fminf(a1, v); a1 = fmaxf(a1, v); a2 = fmaxf(a2, lo);
            v = v0.z; lo = fminf(a1, v); a1 = fmaxf(a1, v); a2 = fmaxf(a2, lo);
            v = v0.w; lo = fminf(a1, v); a1 = fmaxf(a1, v); a2 = fmaxf(a2, lo);
            v = v1.x; lo = fminf(a1, v); a1 = fmaxf(a1, v); a2 = fmaxf(a2, lo);
            v = v1.y; lo = fminf(a1, v); a1 = fmaxf(a1, v); a2 = fmaxf(a2, lo);
            v = v1.z; lo = fminf(a1, v); a1 = fmaxf(a1, v); a2 = fmaxf(a2, lo);
            v = v1.w; lo = fminf(a1, v); a1 = fmaxf(a1, v); a2 = fmaxf(a2, lo);
        }

        // ---- warp top-2 reduce ----
        float w1 = a1, w2 = a2;
        #pragma unroll
        for (int off = 16; off > 0; off >>= 1) {
            float b1 = __shfl_down_sync(0xffffffffu, w1, off);
            float b2 = __shfl_down_sync(0xffffffffu, w2, off);
            float lo = fminf(w1, b1);
            w1 = fmaxf(w1, b1);
            w2 = fmaxf(fmaxf(w2, b2), lo);
        }
        if (lane == 0) { sm1[wid] = w1; sm2[wid] = w2; }
        __syncthreads();                                    // sync1 (slot s fully read)

        // ---- refill slot s with row+2*GRID (DMA runs under the phases below)
        if (tid == 0) {
            int r2 = row + 2 * GRID;
            if (r2 < nrows) {
                mbar_expect_tx(mb, ROW_BYTES);
                bulk_g2s(rg, X + (size_t)r2 * D, mb);
            }
        }

        // ---- warp 0 ONLY: combine 16 partials + branchless unrolled bisect
        if (wid == 0) {
            float M = sm1[lane & (NWARPS - 1)];
            float S = sm2[lane & (NWARPS - 1)];
            #pragma unroll
            for (int off = 8; off > 0; off >>= 1) {
                float b1 = __shfl_xor_sync(0xffffffffu, M, off);
                float b2 = __shfl_xor_sync(0xffffffffu, S, off);
                float lo = fminf(M, b1);
                M = fmaxf(M, b1);
                S = fmaxf(fmaxf(S, b2), lo);
            }
            M *= 0.5f;                       // exact: top-2 of Xs = 0.5*top-2 of X
            S *= 0.5f;
            float tmin = M - 1.0f;
            float diff = (M - 0.015625f) - tmin;   // tmax - tmin
            float t = tmin;
            #pragma unroll
            for (int i = 0; i < N_ITER; i++) {
                diff = diff * 0.5f;          // exact, independent chain
                t = tmin + diff;
                tmin = (S > t) ? t : tmin;   // FSEL, no branch
            }
            if (lane == 0) sbc = t;          // final tested t == reference's
        }
        __syncthreads();                                    // sync2

        const float t = sbc;
        const float p = 1.0f / 4095.0f;      // == fp32(1/(d-1))

        // ---- Z phase (sparsity-guarded, in place over v regs) ----
        const bool active = (fmaf(0.5f, a1, -t) > 0.0f);
        float lsum = 0.0f;
        if (active) {                         // ~1-2 threads per row of 512
            float u;
            u = fmaf(0.5f, v0.x, -t); v0.x = (u > 0.0f) ? __powf(u, p) : 0.0f; lsum += v0.x;
            u = fmaf(0.5f, v0.y, -t); v0.y = (u > 0.0f) ? __powf(u, p) : 0.0f; lsum += v0.y;
            u = fmaf(0.5f, v0.z, -t); v0.z = (u > 0.0f) ? __powf(u, p) : 0.0f; lsum += v0.z;
            u = fmaf(0.5f, v0.w, -t); v0.w = (u > 0.0f) ? __powf(u, p) : 0.0f; lsum += v0.w;
            u = fmaf(0.5f, v1.x, -t); v1.x = (u > 0.0f) ? __powf(u, p) : 0.0f; lsum += v1.x;
            u = fmaf(0.5f, v1.y, -t); v1.y = (u > 0.0f) ? __powf(u, p) : 0.0f; lsum += v1.y;
            u = fmaf(0.5f, v1.z, -t); v1.z = (u > 0.0f) ? __powf(u, p) : 0.0f; lsum += v1.z;
            u = fmaf(0.5f, v1.w, -t); v1.w = (u > 0.0f) ? __powf(u, p) : 0.0f; lsum += v1.w;
        }
        #pragma unroll
        for (int off = 16; off > 0; off >>= 1)
            lsum += __shfl_down_sync(0xffffffffu, lsum, off);
        if (lane == 0) ssum[wid] = lsum;
        __syncthreads();                                    // sync3

        // ---- normalize + store ----
        const size_t ob = (size_t)row * (D / 4);
        if (active) {
            const float4* s4 = reinterpret_cast<const float4*>(ssum);
            float4 A = s4[0], B = s4[1], C = s4[2], E = s4[3];
            float tot = ((A.x + A.y) + (A.z + A.w)) + ((B.x + B.y) + (B.z + B.w))
                      + ((C.x + C.y) + (C.z + C.w)) + ((E.x + E.y) + (E.z + E.w));
            const float inv = 1.0f / tot;
            float4 r0, r1;
            r0.x = v0.x * inv; r0.y = v0.y * inv; r0.z = v0.z * inv; r0.w = v0.w * inv;
            r1.x = v1.x * inv; r1.y = v1.y * inv; r1.z = v1.z * inv; r1.w = v1.w * inv;
            __stcs(&o4[ob + tid], r0);
            __stcs(&o4[ob + tid + THREADS], r1);
        } else {
            const float4 zr = make_float4(0.0f, 0.0f, 0.0f, 0.0f);
            __stcs(&o4[ob + tid], zr);
            __stcs(&o4[ob + tid + THREADS], zr);
        }

        if (!more) break;
        row += GRID;
        j++;
    }
}

extern "C" void kernel_launch(void* const* d_in, const int* in_sizes, int n_in,
                              void* d_out, int out_size)
{
    const float* X = (const float*)d_in[0];
    float* out = (float*)d_out;
    const int n = in_sizes[0];          // 8*2048*4096
    const int rows = n / D;             // 16384
    entmax_bisect_kernel<<<GRID, THREADS>>>(X, out, rows);
}